// round 3
// baseline (speedup 1.0000x reference)
#include <cuda_runtime.h>

#define H 512
#define NH 8
#define HD 64
#define LSEQ 2048
#define BATCH 4
#define M_TOK (BATCH * LSEQ)   // 8192

// ---------------------------------------------------------------------------
// Scratch (static device allocations; no cudaMalloc allowed)
// ---------------------------------------------------------------------------
__device__ float g_Wqt[H * H];
__device__ float g_Wkt[H * H];
__device__ float g_Wvt[H * H];
__device__ float g_Wrt[H * H];
__device__ float g_q[M_TOK * H];
__device__ float g_k[M_TOK * H];
__device__ float g_v[M_TOK * H];
__device__ float g_r[LSEQ * H];
__device__ float g_att[M_TOK * H];
__device__ float g_c[M_TOK * H];
__device__ float g_a[M_TOK * H];
__device__ float g_h1[M_TOK * H];
__device__ float g_h2[M_TOK * H];

// ---------------------------------------------------------------------------
// Weight transpose: W[n][h][d] -> Wt[c][h], c = n*64+d  (all 4 head weights)
// ---------------------------------------------------------------------------
__global__ void transpose_w(const float* __restrict__ Wq, const float* __restrict__ Wk,
                            const float* __restrict__ Wv, const float* __restrict__ Wr)
{
    int idx = blockIdx.x * blockDim.x + threadIdx.x;   // 4 * 512 * 512 total
    int w   = idx >> 18;
    int e   = idx & 262143;
    int c   = e >> 9;
    int h   = e & 511;
    int n   = c >> 6;
    int d   = c & 63;
    int src = n * (H * HD) + h * HD + d;
    float val;
    float* dst;
    if (w == 0)      { val = Wq[src]; dst = g_Wqt; }
    else if (w == 1) { val = Wk[src]; dst = g_Wkt; }
    else if (w == 2) { val = Wv[src]; dst = g_Wvt; }
    else             { val = Wr[src]; dst = g_Wrt; }
    dst[e] = val;
}

// ---------------------------------------------------------------------------
// NT SGEMM: C[m][j] = sum_k A[m][k] * Bw[j][k] + bias[j]
// BM=BN=128, BK=8, 256 threads, 8x8 micro-tile. EPI==1 -> GELU epilogue.
// M = gridDim.y*128, Nc = gridDim.x*128, K multiple of 8.
// ---------------------------------------------------------------------------
__device__ __forceinline__ float gelu_f(float v) {
    return v * 0.5f * (1.0f + erff(v * 0.7071067811865476f));
}

template <int EPI>
__global__ __launch_bounds__(256) void gemm_nt(
    const float* __restrict__ A, const float* __restrict__ Bw,
    const float* __restrict__ bias, float* __restrict__ C, int K)
{
    __shared__ float As[8][128];
    __shared__ float Bs[8][128];

    const int tid = threadIdx.x;
    const int m0  = blockIdx.y * 128;
    const int n0  = blockIdx.x * 128;
    const int Nc  = gridDim.x * 128;
    const int tm  = tid >> 4;
    const int tn  = tid & 15;
    const int lr  = tid >> 1;           // 0..127
    const int lk  = (tid & 1) << 2;     // 0 or 4

    const float* Ap = A  + (size_t)(m0 + lr) * K + lk;
    const float* Bp = Bw + (size_t)(n0 + lr) * K + lk;

    float acc[8][8];
#pragma unroll
    for (int i = 0; i < 8; i++)
#pragma unroll
        for (int j = 0; j < 8; j++) acc[i][j] = 0.0f;

    float4 a4 = *(const float4*)Ap;
    float4 b4 = *(const float4*)Bp;

    for (int k0 = 0; k0 < K; k0 += 8) {
        __syncthreads();
        As[lk + 0][lr] = a4.x; As[lk + 1][lr] = a4.y;
        As[lk + 2][lr] = a4.z; As[lk + 3][lr] = a4.w;
        Bs[lk + 0][lr] = b4.x; Bs[lk + 1][lr] = b4.y;
        Bs[lk + 2][lr] = b4.z; Bs[lk + 3][lr] = b4.w;
        __syncthreads();
        if (k0 + 8 < K) {
            a4 = *(const float4*)(Ap + k0 + 8);
            b4 = *(const float4*)(Bp + k0 + 8);
        }
#pragma unroll
        for (int kk = 0; kk < 8; kk++) {
            float4 af0 = *(const float4*)&As[kk][tm * 8];
            float4 af1 = *(const float4*)&As[kk][tm * 8 + 4];
            float4 bf0 = *(const float4*)&Bs[kk][tn * 8];
            float4 bf1 = *(const float4*)&Bs[kk][tn * 8 + 4];
            float av[8] = {af0.x, af0.y, af0.z, af0.w, af1.x, af1.y, af1.z, af1.w};
            float bv[8] = {bf0.x, bf0.y, bf0.z, bf0.w, bf1.x, bf1.y, bf1.z, bf1.w};
#pragma unroll
            for (int i = 0; i < 8; i++)
#pragma unroll
                for (int j = 0; j < 8; j++)
                    acc[i][j] = fmaf(av[i], bv[j], acc[i][j]);
        }
    }

#pragma unroll
    for (int i = 0; i < 8; i++) {
        const int row = m0 + tm * 8 + i;
        float* Cp = C + (size_t)row * Nc + n0 + tn * 8;
#pragma unroll
        for (int j = 0; j < 8; j += 4) {
            float t0 = acc[i][j + 0] + bias[n0 + tn * 8 + j + 0];
            float t1 = acc[i][j + 1] + bias[n0 + tn * 8 + j + 1];
            float t2 = acc[i][j + 2] + bias[n0 + tn * 8 + j + 2];
            float t3 = acc[i][j + 3] + bias[n0 + tn * 8 + j + 3];
            if (EPI == 1) {
                t0 = gelu_f(t0); t1 = gelu_f(t1);
                t2 = gelu_f(t2); t3 = gelu_f(t3);
            }
            *(float4*)(Cp + j) = make_float4(t0, t1, t2, t3);
        }
    }
}

// ---------------------------------------------------------------------------
// Flash attention with Transformer-XL relative positions (causal).
// For j<=i: S[i][j] = (qc_i . k_j + qp_i . r[L-1-i+j]) / 8
// Grid: (L/64, N, B), 256 threads, 64-row query tile, 64-col key tiles.
// ---------------------------------------------------------------------------
__global__ __launch_bounds__(256) void attn_kernel(
    const float* __restrict__ q, const float* __restrict__ k,
    const float* __restrict__ v, const float* __restrict__ r,
    const float* __restrict__ cb, const float* __restrict__ pb,
    float* __restrict__ outp)
{
    extern __shared__ float smf[];
    float* qcT = smf;                    // [64][68]  (d-major, padded)
    float* qpT = smf + 4352;             // [64][68]
    float* kT  = smf + 2 * 4352;         // [64][68]  (aliased by Ps[64][64])
    float* vs  = smf + 3 * 4352;         // [64][64]  (row-major [j][d])
    float* rT  = smf + 3 * 4352 + 4096;  // [64][132] (d-major, 128 rel rows)
    float* Ps  = kT;

    const int i0  = blockIdx.x * 64;
    const int n   = blockIdx.y;
    const int b   = blockIdx.z;
    const int tid = threadIdx.x;
    const int tm  = tid >> 4;
    const int tn  = tid & 15;
    const int d4  = tn * 4;

    const float* qb = q + (size_t)b * LSEQ * H + n * HD;
    const float* kb = k + (size_t)b * LSEQ * H + n * HD;
    const float* vb = v + (size_t)b * LSEQ * H + n * HD;
    const float* rg = r + n * HD;

    // Load qc/qp tiles, transposed, with content/pos bias added.
    {
        float cbv[4], pbv[4];
#pragma unroll
        for (int s = 0; s < 4; s++) {
            cbv[s] = cb[n * HD + d4 + s];
            pbv[s] = pb[n * HD + d4 + s];
        }
#pragma unroll
        for (int p = 0; p < 4; p++) {
            int row = tm + p * 16;
            float4 qv = *(const float4*)(qb + (size_t)(i0 + row) * H + d4);
            qcT[(d4 + 0) * 68 + row] = qv.x + cbv[0];
            qcT[(d4 + 1) * 68 + row] = qv.y + cbv[1];
            qcT[(d4 + 2) * 68 + row] = qv.z + cbv[2];
            qcT[(d4 + 3) * 68 + row] = qv.w + cbv[3];
            qpT[(d4 + 0) * 68 + row] = qv.x + pbv[0];
            qpT[(d4 + 1) * 68 + row] = qv.y + pbv[1];
            qpT[(d4 + 2) * 68 + row] = qv.z + pbv[2];
            qpT[(d4 + 3) * 68 + row] = qv.w + pbv[3];
        }
    }

    float mrow[4], lrow[4], o[4][4];
#pragma unroll
    for (int a = 0; a < 4; a++) {
        mrow[a] = -1e30f;
        lrow[a] = 0.0f;
#pragma unroll
        for (int c = 0; c < 4; c++) o[a][c] = 0.0f;
    }

    const int ntiles = (i0 >> 6) + 1;
    const int rb = 60 - tm * 4 + tn * 4;   // rel-row base for this thread's 4x4 tile

    for (int t = 0; t < ntiles; t++) {
        const int j0 = t << 6;
        __syncthreads();   // previous PV reads of Ps/vs complete

        // Load K (transposed), V (row-major), R window (transposed)
#pragma unroll
        for (int p = 0; p < 4; p++) {
            int row = tm + p * 16;
            float4 kv = *(const float4*)(kb + (size_t)(j0 + row) * H + d4);
            kT[(d4 + 0) * 68 + row] = kv.x;
            kT[(d4 + 1) * 68 + row] = kv.y;
            kT[(d4 + 2) * 68 + row] = kv.z;
            kT[(d4 + 3) * 68 + row] = kv.w;
            float4 vv = *(const float4*)(vb + (size_t)(j0 + row) * H + d4);
            *(float4*)&vs[row * 64 + d4] = vv;
        }
        const int pb0 = LSEQ - 64 - i0 + j0;   // p(idx) = pb0 + idx, idx in [0,128)
#pragma unroll
        for (int p = 0; p < 8; p++) {
            int idx  = tm + p * 16;
            int prow = pb0 + idx;
            float4 rv = make_float4(0.f, 0.f, 0.f, 0.f);
            if (prow < LSEQ)
                rv = *(const float4*)(rg + (size_t)prow * H + d4);
            rT[(d4 + 0) * 132 + idx] = rv.x;
            rT[(d4 + 1) * 132 + idx] = rv.y;
            rT[(d4 + 2) * 132 + idx] = rv.z;
            rT[(d4 + 3) * 132 + idx] = rv.w;
        }
        __syncthreads();

        // S = qc.K^T + qp.R_band^T
        float s[4][4];
#pragma unroll
        for (int a = 0; a < 4; a++)
#pragma unroll
            for (int c = 0; c < 4; c++) s[a][c] = 0.0f;

#pragma unroll 8
        for (int d = 0; d < 64; d++) {
            float4 qcf = *(const float4*)&qcT[d * 68 + tm * 4];
            float4 qpf = *(const float4*)&qpT[d * 68 + tm * 4];
            float4 kf  = *(const float4*)&kT[d * 68 + tn * 4];
            float4 r0  = *(const float4*)&rT[d * 132 + rb];
            float4 r1  = *(const float4*)&rT[d * 132 + rb + 4];
            float qcv[4] = {qcf.x, qcf.y, qcf.z, qcf.w};
            float qpv[4] = {qpf.x, qpf.y, qpf.z, qpf.w};
            float kv_[4] = {kf.x, kf.y, kf.z, kf.w};
            float rv_[8] = {r0.x, r0.y, r0.z, r0.w, r1.x, r1.y, r1.z, r1.w};
#pragma unroll
            for (int a = 0; a < 4; a++)
#pragma unroll
                for (int c = 0; c < 4; c++)
                    s[a][c] += qcv[a] * kv_[c] + qpv[a] * rv_[c - a + 3];
        }

        const bool diag = (t == ntiles - 1);
#pragma unroll
        for (int a = 0; a < 4; a++)
#pragma unroll
            for (int c = 0; c < 4; c++) {
                s[a][c] *= 0.125f;
                if (diag && (j0 + tn * 4 + c > i0 + tm * 4 + a))
                    s[a][c] = -1e30f;
            }

        // Online softmax (row groups = 16 lanes with same tm within warp)
#pragma unroll
        for (int a = 0; a < 4; a++) {
            float mt = fmaxf(fmaxf(s[a][0], s[a][1]), fmaxf(s[a][2], s[a][3]));
#pragma unroll
            for (int off = 8; off; off >>= 1)
                mt = fmaxf(mt, __shfl_xor_sync(0xffffffffu, mt, off));
            float mnew = fmaxf(mrow[a], mt);
            float corr = __expf(mrow[a] - mnew);
            float ps = 0.0f;
#pragma unroll
            for (int c = 0; c < 4; c++) {
                float pvv = __expf(s[a][c] - mnew);
                s[a][c] = pvv;
                ps += pvv;
            }
#pragma unroll
            for (int off = 8; off; off >>= 1)
                ps += __shfl_xor_sync(0xffffffffu, ps, off);
            lrow[a] = lrow[a] * corr + ps;
            mrow[a] = mnew;
#pragma unroll
            for (int c = 0; c < 4; c++) o[a][c] *= corr;
        }

        __syncthreads();   // all S reads of kT done before Ps overwrites it
#pragma unroll
        for (int a = 0; a < 4; a++)
            *(float4*)&Ps[(tm * 4 + a) * 64 + tn * 4] =
                make_float4(s[a][0], s[a][1], s[a][2], s[a][3]);
        __syncthreads();

        // O += P.V
#pragma unroll 8
        for (int j = 0; j < 64; j++) {
            float4 vf = *(const float4*)&vs[j * 64 + tn * 4];
            float pv[4];
#pragma unroll
            for (int a = 0; a < 4; a++) pv[a] = Ps[(tm * 4 + a) * 64 + j];
#pragma unroll
            for (int a = 0; a < 4; a++) {
                o[a][0] += pv[a] * vf.x;
                o[a][1] += pv[a] * vf.y;
                o[a][2] += pv[a] * vf.z;
                o[a][3] += pv[a] * vf.w;
            }
        }
    }

    // Normalize and write out[b][i][n*64+d]
    float* ob = outp + (size_t)b * LSEQ * H + n * HD;
#pragma unroll
    for (int a = 0; a < 4; a++) {
        float inv = 1.0f / lrow[a];
        *(float4*)(ob + (size_t)(i0 + tm * 4 + a) * H + tn * 4) =
            make_float4(o[a][0] * inv, o[a][1] * inv, o[a][2] * inv, o[a][3] * inv);
    }
}

// ---------------------------------------------------------------------------
// LayerNorm over last dim (512): out = w * (y+res - mean)/sqrt(var+1e-12) + b
// One block per row, 128 threads x float4.
// ---------------------------------------------------------------------------
__global__ __launch_bounds__(128) void layernorm_k(
    const float* __restrict__ yv, const float* __restrict__ res,
    const float* __restrict__ w, const float* __restrict__ bb,
    float* __restrict__ outp)
{
    __shared__ float red[4];
    const int row = blockIdx.x;
    const int t   = threadIdx.x;
    const float4 y4 = ((const float4*)(yv + (size_t)row * H))[t];
    const float4 r4 = ((const float4*)(res + (size_t)row * H))[t];
    const float ax = y4.x + r4.x, ay = y4.y + r4.y;
    const float az = y4.z + r4.z, aw = y4.w + r4.w;

    float s = ax + ay + az + aw;
#pragma unroll
    for (int off = 16; off; off >>= 1) s += __shfl_xor_sync(0xffffffffu, s, off);
    if ((t & 31) == 0) red[t >> 5] = s;
    __syncthreads();
    const float mean = (red[0] + red[1] + red[2] + red[3]) * (1.0f / 512.0f);

    const float dx = ax - mean, dy = ay - mean, dz = az - mean, dw = aw - mean;
    float s2 = dx * dx + dy * dy + dz * dz + dw * dw;
#pragma unroll
    for (int off = 16; off; off >>= 1) s2 += __shfl_xor_sync(0xffffffffu, s2, off);
    __syncthreads();
    if ((t & 31) == 0) red[t >> 5] = s2;
    __syncthreads();
    const float var = (red[0] + red[1] + red[2] + red[3]) * (1.0f / 512.0f);
    const float inv = rsqrtf(var + 1e-12f);

    const float4 wv = ((const float4*)w)[t];
    const float4 bv = ((const float4*)bb)[t];
    float4 o;
    o.x = wv.x * dx * inv + bv.x;
    o.y = wv.y * dy * inv + bv.y;
    o.z = wv.z * dz * inv + bv.z;
    o.w = wv.w * dw * inv + bv.w;
    ((float4*)(outp + (size_t)row * H))[t] = o;
}

// ---------------------------------------------------------------------------
// Launch
// ---------------------------------------------------------------------------
extern "C" void kernel_launch(void* const* d_in, const int* in_sizes, int n_in,
                              void* d_out, int out_size)
{
    (void)in_sizes; (void)n_in; (void)out_size;
    const float* x   = (const float*)d_in[0];
    const float* pe  = (const float*)d_in[1];
    const float* Wq  = (const float*)d_in[2];
    const float* bq  = (const float*)d_in[3];
    const float* Wk  = (const float*)d_in[4];
    const float* bk  = (const float*)d_in[5];
    const float* Wv  = (const float*)d_in[6];
    const float* bv  = (const float*)d_in[7];
    const float* Wr  = (const float*)d_in[8];
    const float* br  = (const float*)d_in[9];
    const float* cbv = (const float*)d_in[10];
    const float* pbv = (const float*)d_in[11];
    const float* Wc  = (const float*)d_in[12];
    const float* bc  = (const float*)d_in[13];
    const float* W1  = (const float*)d_in[14];
    const float* b1  = (const float*)d_in[15];
    const float* W2  = (const float*)d_in[16];
    const float* b2  = (const float*)d_in[17];
    const float* lnw = (const float*)d_in[18];
    const float* lnb = (const float*)d_in[19];
    // d_in[20] = mask: deterministically triu(k=1); causality handled in-kernel.
    float* out = (float*)d_out;

    float *q, *k, *v, *r, *att, *cbuf, *abuf, *h1, *h2;
    float *wqt, *wkt, *wvt, *wrt;
    cudaGetSymbolAddress((void**)&q,    g_q);
    cudaGetSymbolAddress((void**)&k,    g_k);
    cudaGetSymbolAddress((void**)&v,    g_v);
    cudaGetSymbolAddress((void**)&r,    g_r);
    cudaGetSymbolAddress((void**)&att,  g_att);
    cudaGetSymbolAddress((void**)&cbuf, g_c);
    cudaGetSymbolAddress((void**)&abuf, g_a);
    cudaGetSymbolAddress((void**)&h1,   g_h1);
    cudaGetSymbolAddress((void**)&h2,   g_h2);
    cudaGetSymbolAddress((void**)&wqt,  g_Wqt);
    cudaGetSymbolAddress((void**)&wkt,  g_Wkt);
    cudaGetSymbolAddress((void**)&wvt,  g_Wvt);
    cudaGetSymbolAddress((void**)&wrt,  g_Wrt);

    // 1) Weight transposes for head projections
    transpose_w<<<4096, 256>>>(Wq, Wk, Wv, Wr);

    // 2) Projections: q,k,v (8192x512x512), r (2048x512x512)
    dim3 gp(4, 64);
    gemm_nt<0><<<gp, 256>>>(x, wqt, bq, q, H);
    gemm_nt<0><<<gp, 256>>>(x, wkt, bk, k, H);
    gemm_nt<0><<<gp, 256>>>(x, wvt, bv, v, H);
    gemm_nt<0><<<dim3(4, 16), 256>>>(pe, wrt, br, r, H);

    // 3) Flash attention with rel-pos
    const int att_smem = 102400;
    cudaFuncSetAttribute(attn_kernel,
                         cudaFuncAttributeMaxDynamicSharedMemorySize, att_smem);
    attn_kernel<<<dim3(32, NH, BATCH), 256, att_smem>>>(q, k, v, r, cbv, pbv, att);

    // 4) Output projection + residual LN
    gemm_nt<0><<<gp, 256>>>(att, Wc, bc, cbuf, H);
    layernorm_k<<<M_TOK, 128>>>(cbuf, x, lnw, lnb, abuf);

    // 5) FFN: gelu(a@W1^T+b1)@W2^T+b2, then final residual LN -> out
    gemm_nt<1><<<gp, 256>>>(abuf, W1, b1, h1, H);
    gemm_nt<0><<<gp, 256>>>(h1, W2, b2, h2, H);
    layernorm_k<<<M_TOK, 128>>>(h2, abuf, lnw, lnb, out);
}

// round 4
// speedup vs baseline: 1.2738x; 1.2738x over previous
#include <cuda_runtime.h>

#define H 512
#define NH 8
#define HD 64
#define LSEQ 2048
#define BATCH 4
#define M_TOK (BATCH * LSEQ)   // 8192

// ---------------------------------------------------------------------------
// Scratch (static device allocations; no cudaMalloc allowed)
// ---------------------------------------------------------------------------
__device__ float g_Wqt[H * H];
__device__ float g_Wkt[H * H];
__device__ float g_Wvt[H * H];
__device__ float g_Wrt[H * H];
__device__ float g_q[M_TOK * H];
__device__ float g_k[M_TOK * H];
__device__ float g_v[M_TOK * H];
__device__ float g_r[LSEQ * H];
__device__ float g_att[M_TOK * H];
__device__ float g_c[M_TOK * H];
__device__ float g_a[M_TOK * H];
__device__ float g_h1[M_TOK * H];
__device__ float g_h2[M_TOK * H];

// ---------------------------------------------------------------------------
// Weight transpose: W[n][h][d] -> Wt[c][h], c = n*64+d  (all 4 head weights)
// ---------------------------------------------------------------------------
__global__ void transpose_w(const float* __restrict__ Wq, const float* __restrict__ Wk,
                            const float* __restrict__ Wv, const float* __restrict__ Wr)
{
    int idx = blockIdx.x * blockDim.x + threadIdx.x;   // 4 * 512 * 512 total
    int w   = idx >> 18;
    int e   = idx & 262143;
    int c   = e >> 9;
    int h   = e & 511;
    int n   = c >> 6;
    int d   = c & 63;
    int src = n * (H * HD) + h * HD + d;
    float val;
    float* dst;
    if (w == 0)      { val = Wq[src]; dst = g_Wqt; }
    else if (w == 1) { val = Wk[src]; dst = g_Wkt; }
    else if (w == 2) { val = Wv[src]; dst = g_Wvt; }
    else             { val = Wr[src]; dst = g_Wrt; }
    dst[e] = val;
}

// ---------------------------------------------------------------------------
// TF32 tensor-core NT GEMM: C[m][j] = sum_k A[m][k]*Bw[j][k] + bias[j]
// Block tile 128x128, BK=32, 256 threads = 8 warps (2x4), warp tile 64x32.
// mma.sync.aligned.m16n8k8.row.col.f32.tf32.tf32.f32
// Smem layout: [row][32 + 4 pad] -> conflict-free frag loads (4*gid+tig).
// ---------------------------------------------------------------------------
__device__ __forceinline__ float gelu_f(float v) {
    return v * 0.5f * (1.0f + erff(v * 0.7071067811865476f));
}

__device__ __forceinline__ unsigned tf32r(float x) {
    unsigned u;
    asm("cvt.rna.tf32.f32 %0, %1;" : "=r"(u) : "f"(x));
    return u;
}

__device__ __forceinline__ void mma_tf32(float* c, const unsigned* a, const unsigned* b) {
    asm volatile(
        "mma.sync.aligned.m16n8k8.row.col.f32.tf32.tf32.f32 "
        "{%0,%1,%2,%3}, {%4,%5,%6,%7}, {%8,%9}, {%0,%1,%2,%3};\n"
        : "+f"(c[0]), "+f"(c[1]), "+f"(c[2]), "+f"(c[3])
        : "r"(a[0]), "r"(a[1]), "r"(a[2]), "r"(a[3]), "r"(b[0]), "r"(b[1]));
}

template <int EPI>
__global__ __launch_bounds__(256) void gemm_tf32(
    const float* __restrict__ A, const float* __restrict__ Bw,
    const float* __restrict__ bias, float* __restrict__ C, int K)
{
    __shared__ float As[128 * 36];
    __shared__ float Bs[128 * 36];

    const int tid  = threadIdx.x;
    const int m0   = blockIdx.y * 128;
    const int n0   = blockIdx.x * 128;
    const int Nc   = gridDim.x * 128;
    const int lane = tid & 31;
    const int wid  = tid >> 5;
    const int gid  = lane >> 2;   // 0..7
    const int tig  = lane & 3;    // 0..3
    const int wm   = (wid & 1) * 64;
    const int wn   = (wid >> 1) * 32;

    // Staging mapping: thread handles rows (tid>>3)+32*i, k-chunk 4*(tid&7)
    const int srow = tid >> 3;       // 0..31
    const int skc  = (tid & 7) * 4;  // 0,4,...,28

    float acc[4][4][4];
#pragma unroll
    for (int mt = 0; mt < 4; mt++)
#pragma unroll
        for (int nt = 0; nt < 4; nt++)
#pragma unroll
            for (int e = 0; e < 4; e++) acc[mt][nt][e] = 0.0f;

    float4 pa[4], pb[4];
#pragma unroll
    for (int i = 0; i < 4; i++) {
        pa[i] = *(const float4*)(A  + (size_t)(m0 + srow + 32 * i) * K + skc);
        pb[i] = *(const float4*)(Bw + (size_t)(n0 + srow + 32 * i) * K + skc);
    }

    for (int k0 = 0; k0 < K; k0 += 32) {
        __syncthreads();
#pragma unroll
        for (int i = 0; i < 4; i++) {
            float* ap = &As[(srow + 32 * i) * 36 + skc];
            ap[0] = __uint_as_float(tf32r(pa[i].x));
            ap[1] = __uint_as_float(tf32r(pa[i].y));
            ap[2] = __uint_as_float(tf32r(pa[i].z));
            ap[3] = __uint_as_float(tf32r(pa[i].w));
            float* bp = &Bs[(srow + 32 * i) * 36 + skc];
            bp[0] = __uint_as_float(tf32r(pb[i].x));
            bp[1] = __uint_as_float(tf32r(pb[i].y));
            bp[2] = __uint_as_float(tf32r(pb[i].z));
            bp[3] = __uint_as_float(tf32r(pb[i].w));
        }
        __syncthreads();

        if (k0 + 32 < K) {
#pragma unroll
            for (int i = 0; i < 4; i++) {
                pa[i] = *(const float4*)(A  + (size_t)(m0 + srow + 32 * i) * K + k0 + 32 + skc);
                pb[i] = *(const float4*)(Bw + (size_t)(n0 + srow + 32 * i) * K + k0 + 32 + skc);
            }
        }

#pragma unroll
        for (int ks = 0; ks < 4; ks++) {
            const int kk = ks * 8;
            unsigned af[4][4], bf[4][2];
#pragma unroll
            for (int mt = 0; mt < 4; mt++) {
                const int mr = wm + mt * 16 + gid;
                af[mt][0] = __float_as_uint(As[mr * 36 + kk + tig]);
                af[mt][1] = __float_as_uint(As[(mr + 8) * 36 + kk + tig]);
                af[mt][2] = __float_as_uint(As[mr * 36 + kk + tig + 4]);
                af[mt][3] = __float_as_uint(As[(mr + 8) * 36 + kk + tig + 4]);
            }
#pragma unroll
            for (int nt = 0; nt < 4; nt++) {
                const int nr = wn + nt * 8 + gid;
                bf[nt][0] = __float_as_uint(Bs[nr * 36 + kk + tig]);
                bf[nt][1] = __float_as_uint(Bs[nr * 36 + kk + tig + 4]);
            }
#pragma unroll
            for (int mt = 0; mt < 4; mt++)
#pragma unroll
                for (int nt = 0; nt < 4; nt++)
                    mma_tf32(acc[mt][nt], af[mt], bf[nt]);
        }
    }

    // Epilogue: c0=(gid,2tig) c1=(gid,2tig+1) c2=(gid+8,2tig) c3=(gid+8,2tig+1)
#pragma unroll
    for (int mt = 0; mt < 4; mt++) {
        const int r0 = m0 + wm + mt * 16 + gid;
#pragma unroll
        for (int nt = 0; nt < 4; nt++) {
            const int c = n0 + wn + nt * 8 + tig * 2;
            const float b0 = bias[c], b1 = bias[c + 1];
            float d0 = acc[mt][nt][0] + b0;
            float d1 = acc[mt][nt][1] + b1;
            float d2 = acc[mt][nt][2] + b0;
            float d3 = acc[mt][nt][3] + b1;
            if (EPI == 1) {
                d0 = gelu_f(d0); d1 = gelu_f(d1);
                d2 = gelu_f(d2); d3 = gelu_f(d3);
            }
            *(float2*)(C + (size_t)r0 * Nc + c)       = make_float2(d0, d1);
            *(float2*)(C + (size_t)(r0 + 8) * Nc + c) = make_float2(d2, d3);
        }
    }
}

// ---------------------------------------------------------------------------
// Flash attention with Transformer-XL relative positions (causal), fp32.
// For j<=i: S[i][j] = (qc_i . k_j + qp_i . r[L-1-i+j]) / 8
// Grid: (L/64, N, B), 256 threads, 64-row query tile, 64-col key tiles.
// ---------------------------------------------------------------------------
__global__ __launch_bounds__(256) void attn_kernel(
    const float* __restrict__ q, const float* __restrict__ k,
    const float* __restrict__ v, const float* __restrict__ r,
    const float* __restrict__ cb, const float* __restrict__ pb,
    float* __restrict__ outp)
{
    extern __shared__ float smf[];
    float* qcT = smf;                    // [64][68]  (d-major, padded)
    float* qpT = smf + 4352;             // [64][68]
    float* kT  = smf + 2 * 4352;         // [64][68]  (aliased by Ps[64][64])
    float* vs  = smf + 3 * 4352;         // [64][64]  (row-major [j][d])
    float* rT  = smf + 3 * 4352 + 4096;  // [64][132] (d-major, 128 rel rows)
    float* Ps  = kT;

    const int i0  = blockIdx.x * 64;
    const int n   = blockIdx.y;
    const int b   = blockIdx.z;
    const int tid = threadIdx.x;
    const int tm  = tid >> 4;
    const int tn  = tid & 15;
    const int d4  = tn * 4;

    const float* qb = q + (size_t)b * LSEQ * H + n * HD;
    const float* kb = k + (size_t)b * LSEQ * H + n * HD;
    const float* vb = v + (size_t)b * LSEQ * H + n * HD;
    const float* rg = r + n * HD;

    {
        float cbv[4], pbv[4];
#pragma unroll
        for (int s = 0; s < 4; s++) {
            cbv[s] = cb[n * HD + d4 + s];
            pbv[s] = pb[n * HD + d4 + s];
        }
#pragma unroll
        for (int p = 0; p < 4; p++) {
            int row = tm + p * 16;
            float4 qv = *(const float4*)(qb + (size_t)(i0 + row) * H + d4);
            qcT[(d4 + 0) * 68 + row] = qv.x + cbv[0];
            qcT[(d4 + 1) * 68 + row] = qv.y + cbv[1];
            qcT[(d4 + 2) * 68 + row] = qv.z + cbv[2];
            qcT[(d4 + 3) * 68 + row] = qv.w + cbv[3];
            qpT[(d4 + 0) * 68 + row] = qv.x + pbv[0];
            qpT[(d4 + 1) * 68 + row] = qv.y + pbv[1];
            qpT[(d4 + 2) * 68 + row] = qv.z + pbv[2];
            qpT[(d4 + 3) * 68 + row] = qv.w + pbv[3];
        }
    }

    float mrow[4], lrow[4], o[4][4];
#pragma unroll
    for (int a = 0; a < 4; a++) {
        mrow[a] = -1e30f;
        lrow[a] = 0.0f;
#pragma unroll
        for (int c = 0; c < 4; c++) o[a][c] = 0.0f;
    }

    const int ntiles = (i0 >> 6) + 1;
    const int rb = 60 - tm * 4 + tn * 4;

    for (int t = 0; t < ntiles; t++) {
        const int j0 = t << 6;
        __syncthreads();

#pragma unroll
        for (int p = 0; p < 4; p++) {
            int row = tm + p * 16;
            float4 kv = *(const float4*)(kb + (size_t)(j0 + row) * H + d4);
            kT[(d4 + 0) * 68 + row] = kv.x;
            kT[(d4 + 1) * 68 + row] = kv.y;
            kT[(d4 + 2) * 68 + row] = kv.z;
            kT[(d4 + 3) * 68 + row] = kv.w;
            float4 vv = *(const float4*)(vb + (size_t)(j0 + row) * H + d4);
            *(float4*)&vs[row * 64 + d4] = vv;
        }
        const int pb0 = LSEQ - 64 - i0 + j0;
#pragma unroll
        for (int p = 0; p < 8; p++) {
            int idx  = tm + p * 16;
            int prow = pb0 + idx;
            float4 rv = make_float4(0.f, 0.f, 0.f, 0.f);
            if (prow < LSEQ)
                rv = *(const float4*)(rg + (size_t)prow * H + d4);
            rT[(d4 + 0) * 132 + idx] = rv.x;
            rT[(d4 + 1) * 132 + idx] = rv.y;
            rT[(d4 + 2) * 132 + idx] = rv.z;
            rT[(d4 + 3) * 132 + idx] = rv.w;
        }
        __syncthreads();

        float s[4][4];
#pragma unroll
        for (int a = 0; a < 4; a++)
#pragma unroll
            for (int c = 0; c < 4; c++) s[a][c] = 0.0f;

#pragma unroll 8
        for (int d = 0; d < 64; d++) {
            float4 qcf = *(const float4*)&qcT[d * 68 + tm * 4];
            float4 qpf = *(const float4*)&qpT[d * 68 + tm * 4];
            float4 kf  = *(const float4*)&kT[d * 68 + tn * 4];
            float4 r0  = *(const float4*)&rT[d * 132 + rb];
            float4 r1  = *(const float4*)&rT[d * 132 + rb + 4];
            float qcv[4] = {qcf.x, qcf.y, qcf.z, qcf.w};
            float qpv[4] = {qpf.x, qpf.y, qpf.z, qpf.w};
            float kv_[4] = {kf.x, kf.y, kf.z, kf.w};
            float rv_[8] = {r0.x, r0.y, r0.z, r0.w, r1.x, r1.y, r1.z, r1.w};
#pragma unroll
            for (int a = 0; a < 4; a++)
#pragma unroll
                for (int c = 0; c < 4; c++)
                    s[a][c] += qcv[a] * kv_[c] + qpv[a] * rv_[c - a + 3];
        }

        const bool diag = (t == ntiles - 1);
#pragma unroll
        for (int a = 0; a < 4; a++)
#pragma unroll
            for (int c = 0; c < 4; c++) {
                s[a][c] *= 0.125f;
                if (diag && (j0 + tn * 4 + c > i0 + tm * 4 + a))
                    s[a][c] = -1e30f;
            }

#pragma unroll
        for (int a = 0; a < 4; a++) {
            float mt = fmaxf(fmaxf(s[a][0], s[a][1]), fmaxf(s[a][2], s[a][3]));
#pragma unroll
            for (int off = 8; off; off >>= 1)
                mt = fmaxf(mt, __shfl_xor_sync(0xffffffffu, mt, off));
            float mnew = fmaxf(mrow[a], mt);
            float corr = __expf(mrow[a] - mnew);
            float ps = 0.0f;
#pragma unroll
            for (int c = 0; c < 4; c++) {
                float pvv = __expf(s[a][c] - mnew);
                s[a][c] = pvv;
                ps += pvv;
            }
#pragma unroll
            for (int off = 8; off; off >>= 1)
                ps += __shfl_xor_sync(0xffffffffu, ps, off);
            lrow[a] = lrow[a] * corr + ps;
            mrow[a] = mnew;
#pragma unroll
            for (int c = 0; c < 4; c++) o[a][c] *= corr;
        }

        __syncthreads();
#pragma unroll
        for (int a = 0; a < 4; a++)
            *(float4*)&Ps[(tm * 4 + a) * 64 + tn * 4] =
                make_float4(s[a][0], s[a][1], s[a][2], s[a][3]);
        __syncthreads();

#pragma unroll 8
        for (int j = 0; j < 64; j++) {
            float4 vf = *(const float4*)&vs[j * 64 + tn * 4];
            float pv[4];
#pragma unroll
            for (int a = 0; a < 4; a++) pv[a] = Ps[(tm * 4 + a) * 64 + j];
#pragma unroll
            for (int a = 0; a < 4; a++) {
                o[a][0] += pv[a] * vf.x;
                o[a][1] += pv[a] * vf.y;
                o[a][2] += pv[a] * vf.z;
                o[a][3] += pv[a] * vf.w;
            }
        }
    }

    float* ob = outp + (size_t)b * LSEQ * H + n * HD;
#pragma unroll
    for (int a = 0; a < 4; a++) {
        float inv = 1.0f / lrow[a];
        *(float4*)(ob + (size_t)(i0 + tm * 4 + a) * H + tn * 4) =
            make_float4(o[a][0] * inv, o[a][1] * inv, o[a][2] * inv, o[a][3] * inv);
    }
}

// ---------------------------------------------------------------------------
// LayerNorm over last dim (512): out = w * (y+res - mean)/sqrt(var+1e-12) + b
// ---------------------------------------------------------------------------
__global__ __launch_bounds__(128) void layernorm_k(
    const float* __restrict__ yv, const float* __restrict__ res,
    const float* __restrict__ w, const float* __restrict__ bb,
    float* __restrict__ outp)
{
    __shared__ float red[4];
    const int row = blockIdx.x;
    const int t   = threadIdx.x;
    const float4 y4 = ((const float4*)(yv + (size_t)row * H))[t];
    const float4 r4 = ((const float4*)(res + (size_t)row * H))[t];
    const float ax = y4.x + r4.x, ay = y4.y + r4.y;
    const float az = y4.z + r4.z, aw = y4.w + r4.w;

    float s = ax + ay + az + aw;
#pragma unroll
    for (int off = 16; off; off >>= 1) s += __shfl_xor_sync(0xffffffffu, s, off);
    if ((t & 31) == 0) red[t >> 5] = s;
    __syncthreads();
    const float mean = (red[0] + red[1] + red[2] + red[3]) * (1.0f / 512.0f);

    const float dx = ax - mean, dy = ay - mean, dz = az - mean, dw = aw - mean;
    float s2 = dx * dx + dy * dy + dz * dz + dw * dw;
#pragma unroll
    for (int off = 16; off; off >>= 1) s2 += __shfl_xor_sync(0xffffffffu, s2, off);
    __syncthreads();
    if ((t & 31) == 0) red[t >> 5] = s2;
    __syncthreads();
    const float var = (red[0] + red[1] + red[2] + red[3]) * (1.0f / 512.0f);
    const float inv = rsqrtf(var + 1e-12f);

    const float4 wv = ((const float4*)w)[t];
    const float4 bv = ((const float4*)bb)[t];
    float4 o;
    o.x = wv.x * dx * inv + bv.x;
    o.y = wv.y * dy * inv + bv.y;
    o.z = wv.z * dz * inv + bv.z;
    o.w = wv.w * dw * inv + bv.w;
    ((float4*)(outp + (size_t)row * H))[t] = o;
}

// ---------------------------------------------------------------------------
// Launch
// ---------------------------------------------------------------------------
extern "C" void kernel_launch(void* const* d_in, const int* in_sizes, int n_in,
                              void* d_out, int out_size)
{
    (void)in_sizes; (void)n_in; (void)out_size;
    const float* x   = (const float*)d_in[0];
    const float* pe  = (const float*)d_in[1];
    const float* Wq  = (const float*)d_in[2];
    const float* bq  = (const float*)d_in[3];
    const float* Wk  = (const float*)d_in[4];
    const float* bk  = (const float*)d_in[5];
    const float* Wv  = (const float*)d_in[6];
    const float* bv  = (const float*)d_in[7];
    const float* Wr  = (const float*)d_in[8];
    const float* br  = (const float*)d_in[9];
    const float* cbv = (const float*)d_in[10];
    const float* pbv = (const float*)d_in[11];
    const float* Wc  = (const float*)d_in[12];
    const float* bc  = (const float*)d_in[13];
    const float* W1  = (const float*)d_in[14];
    const float* b1  = (const float*)d_in[15];
    const float* W2  = (const float*)d_in[16];
    const float* b2  = (const float*)d_in[17];
    const float* lnw = (const float*)d_in[18];
    const float* lnb = (const float*)d_in[19];
    float* out = (float*)d_out;

    float *q, *k, *v, *r, *att, *cbuf, *abuf, *h1, *h2;
    float *wqt, *wkt, *wvt, *wrt;
    cudaGetSymbolAddress((void**)&q,    g_q);
    cudaGetSymbolAddress((void**)&k,    g_k);
    cudaGetSymbolAddress((void**)&v,    g_v);
    cudaGetSymbolAddress((void**)&r,    g_r);
    cudaGetSymbolAddress((void**)&att,  g_att);
    cudaGetSymbolAddress((void**)&cbuf, g_c);
    cudaGetSymbolAddress((void**)&abuf, g_a);
    cudaGetSymbolAddress((void**)&h1,   g_h1);
    cudaGetSymbolAddress((void**)&h2,   g_h2);
    cudaGetSymbolAddress((void**)&wqt,  g_Wqt);
    cudaGetSymbolAddress((void**)&wkt,  g_Wkt);
    cudaGetSymbolAddress((void**)&wvt,  g_Wvt);
    cudaGetSymbolAddress((void**)&wrt,  g_Wrt);

    // 1) Weight transposes for head projections
    transpose_w<<<4096, 256>>>(Wq, Wk, Wv, Wr);

    // 2) Projections on tensor cores (tf32): q,k,v (8192x512x512), r (2048x512)
    dim3 gp(4, 64);
    gemm_tf32<0><<<gp, 256>>>(x, wqt, bq, q, H);
    gemm_tf32<0><<<gp, 256>>>(x, wkt, bk, k, H);
    gemm_tf32<0><<<gp, 256>>>(x, wvt, bv, v, H);
    gemm_tf32<0><<<dim3(4, 16), 256>>>(pe, wrt, br, r, H);

    // 3) Flash attention with rel-pos (fp32)
    const int att_smem = 102400;
    cudaFuncSetAttribute(attn_kernel,
                         cudaFuncAttributeMaxDynamicSharedMemorySize, att_smem);
    attn_kernel<<<dim3(32, NH, BATCH), 256, att_smem>>>(q, k, v, r, cbv, pbv, att);

    // 4) Output projection + residual LN
    gemm_tf32<0><<<gp, 256>>>(att, Wc, bc, cbuf, H);
    layernorm_k<<<M_TOK, 128>>>(cbuf, x, lnw, lnb, abuf);

    // 5) FFN: gelu(a@W1^T+b1)@W2^T+b2, then final residual LN -> out
    gemm_tf32<1><<<gp, 256>>>(abuf, W1, b1, h1, H);
    gemm_tf32<0><<<gp, 256>>>(h1, W2, b2, h2, H);
    layernorm_k<<<M_TOK, 128>>>(h2, abuf, lnw, lnb, out);
}